// round 7
// baseline (speedup 1.0000x reference)
#include <cuda_runtime.h>
#include <cuda_bf16.h>

// HungarianMatcher cost tensor C[16,900,800], nc=256.
// R6: wave-quantization fix. R5 (grid 900, conc 296) ran W=3.04 waves ->
// quantized to 4 (24% idle tail). Same inner loop, TILE_R=4 per 512-thread
// block -> grid 3600, W=12.16 -> 13 waves (6.9% tail). Block duration drops
// 6.1us -> 1.5us.

constexpr int NC      = 256;
constexpr int TILE_R  = 4;     // query rows per block
constexpr int THREADS = 512;
constexpr int NT_PER  = 2;     // targets per thread (800 = 400 threads * 2)

constexpr float EPS = 1e-7f;

__global__ __launch_bounds__(THREADS, 2)
void matcher_cost_kernel(const float* __restrict__ logits,   // [N, NC]
                         const float* __restrict__ pboxes,   // [N, 4]
                         const int*   __restrict__ labels,   // [nt]
                         const float* __restrict__ tboxes,   // [nt, 4]
                         float*       __restrict__ out,      // [N, nt]
                         int n_rows, int nt)
{
    __shared__ float  s_prob[TILE_R][NC];   // 4KB softmax probs
    __shared__ float4 s_pred[TILE_R][3];    // {cx,cy,w,h},{x0,y0,x1,y1},{area}

    const int tid  = threadIdx.x;
    const int lane = tid & 31;
    const int warp = tid >> 5;
    const int n0   = blockIdx.x * TILE_R;

    // --- This thread's 2 targets -> registers (9 per target, fully derived) ---
    const int  mbase = tid * NT_PER;
    const bool act   = (mbase + NT_PER) <= nt;   // threads 0..399 for nt=800
    float tcx[NT_PER], tcy[NT_PER], tw[NT_PER], th[NT_PER];
    float tx0[NT_PER], ty0[NT_PER], tx1[NT_PER], ty1[NT_PER], ta[NT_PER];
    int   lob[NT_PER];                            // label byte offsets
    if (act) {
        const float4* tb4 = reinterpret_cast<const float4*>(tboxes);
        int2 lb = reinterpret_cast<const int2*>(labels)[tid];
        lob[0] = lb.x * 4; lob[1] = lb.y * 4;
        #pragma unroll
        for (int j = 0; j < NT_PER; j++) {
            float4 b = tb4[mbase + j];
            tcx[j] = b.x; tcy[j] = b.y; tw[j] = b.z; th[j] = b.w;
            float hw = 0.5f * b.z, hh = 0.5f * b.w;
            tx0[j] = b.x - hw; ty0[j] = b.y - hh;
            tx1[j] = b.x + hw; ty1[j] = b.y + hh;
            ta[j]  = b.z * b.w;
        }
    }

    // --- Softmax: warps 0..TILE_R-1 each own one row (256 classes, 8/lane) ---
    const int n = n0 + warp;
    if (warp < TILE_R && n < n_rows) {
        const float4* lr4 = reinterpret_cast<const float4*>(logits + (size_t)n * NC);
        float4 a = lr4[lane];
        float4 b = lr4[lane + 32];
        float mx = fmaxf(fmaxf(fmaxf(a.x, a.y), fmaxf(a.z, a.w)),
                         fmaxf(fmaxf(b.x, b.y), fmaxf(b.z, b.w)));
        #pragma unroll
        for (int o = 16; o > 0; o >>= 1)
            mx = fmaxf(mx, __shfl_xor_sync(0xffffffffu, mx, o));
        a.x = __expf(a.x - mx); a.y = __expf(a.y - mx);
        a.z = __expf(a.z - mx); a.w = __expf(a.w - mx);
        b.x = __expf(b.x - mx); b.y = __expf(b.y - mx);
        b.z = __expf(b.z - mx); b.w = __expf(b.w - mx);
        float sum = (a.x + a.y) + (a.z + a.w) + (b.x + b.y) + (b.z + b.w);
        #pragma unroll
        for (int o = 16; o > 0; o >>= 1)
            sum += __shfl_xor_sync(0xffffffffu, sum, o);
        float inv = __fdividef(1.0f, sum);
        a.x *= inv; a.y *= inv; a.z *= inv; a.w *= inv;
        b.x *= inv; b.y *= inv; b.z *= inv; b.w *= inv;
        float4* pr = reinterpret_cast<float4*>(s_prob[warp]);
        pr[lane]      = a;
        pr[lane + 32] = b;

        if (lane == 0) {
            float4 pb = reinterpret_cast<const float4*>(pboxes)[n];
            float hw = 0.5f * pb.z, hh = 0.5f * pb.w;
            s_pred[warp][0] = pb;
            s_pred[warp][1] = make_float4(pb.x - hw, pb.y - hh, pb.x + hw, pb.y + hh);
            s_pred[warp][2] = make_float4(pb.z * pb.w, 0.f, 0.f, 0.f);
        }
    }
    __syncthreads();

    const int rmax = min(TILE_R, n_rows - n0);

    if (act) {
        // --- Fast path: unrolled rows, 2 targets in registers ---
        float* orow = out + (size_t)n0 * nt + mbase;
        #pragma unroll
        for (int r = 0; r < TILE_R; r++) {
            if (r >= rmax) break;
            const float4 pc = s_pred[r][0];   // broadcast LDS.128
            const float4 px = s_pred[r][1];
            const float  pa = s_pred[r][2].x;
            const char* prb = reinterpret_cast<const char*>(s_prob[r]);

            float res[NT_PER];
            #pragma unroll
            for (int j = 0; j < NT_PER; j++) {
                float p = *reinterpret_cast<const float*>(prb + lob[j]);

                float l1 = fabsf(pc.x - tcx[j]) + fabsf(pc.y - tcy[j])
                         + fabsf(pc.z - tw[j])  + fabsf(pc.w - th[j]);

                float ix = fminf(px.z, tx1[j]) - fmaxf(px.x, tx0[j]);
                float iy = fminf(px.w, ty1[j]) - fmaxf(px.y, ty0[j]);
                float inter = fmaxf(ix, 0.f) * fmaxf(iy, 0.f);
                float uni   = pa + ta[j] - inter;

                // enclosing box via min/max sum identity: cx = (pw+tw) - ix
                float cxv = (pc.z + tw[j]) - ix;
                float cyv = (pc.w + th[j]) - iy;
                float ca  = cxv * cyv;

                // giou = inter/u - (ca-uni)/c == (inter*c + (uni-ca)*u)/(u*c)
                float u = uni + EPS;
                float c = ca + EPS;
                float num = fmaf(uni - ca, u, inter * c);
                float giou = __fdividef(num, u * c);

                res[j] = fmaf(-2.f, giou, fmaf(5.f, l1, -p));
            }
            *reinterpret_cast<float2*>(orow) = make_float2(res[0], res[1]);
            orow += nt;
        }
    } else if (mbase < nt) {
        // generic tail (nt odd; unused for nt=800)
        for (int j = 0; j < NT_PER && mbase + j < nt; j++) {
            int m = mbase + j;
            float4 b = reinterpret_cast<const float4*>(tboxes)[m];
            int lb = labels[m];
            float hw = 0.5f * b.z, hh = 0.5f * b.w;
            float bx0 = b.x - hw, by0 = b.y - hh, bx1 = b.x + hw, by1 = b.y + hh;
            float bar = b.z * b.w;
            for (int r = 0; r < rmax; r++) {
                float4 pc = s_pred[r][0];
                float4 px = s_pred[r][1];
                float  pa = s_pred[r][2].x;
                float p = s_prob[r][lb];
                float l1 = fabsf(pc.x - b.x) + fabsf(pc.y - b.y)
                         + fabsf(pc.z - b.z) + fabsf(pc.w - b.w);
                float ix = fminf(px.z, bx1) - fmaxf(px.x, bx0);
                float iy = fminf(px.w, by1) - fmaxf(px.y, by0);
                float inter = fmaxf(ix, 0.f) * fmaxf(iy, 0.f);
                float uni = pa + bar - inter;
                float iou = __fdividef(inter, uni + EPS);
                float cxv = fmaxf(px.z, bx1) - fminf(px.x, bx0);
                float cyv = fmaxf(px.w, by1) - fminf(px.y, by0);
                float ca = cxv * cyv;
                float giou = iou - __fdividef(ca - uni, ca + EPS);
                out[(size_t)(n0 + r) * nt + m] = 5.f * l1 - p - 2.f * giou;
            }
        }
    }
}

extern "C" void kernel_launch(void* const* d_in, const int* in_sizes, int n_in,
                              void* d_out, int out_size)
{
    const float* logits = (const float*)d_in[0];
    const float* pboxes = (const float*)d_in[1];
    const int*   labels = (const int*)  d_in[2];
    const float* tboxes = (const float*)d_in[3];
    float*       out    = (float*)d_out;

    const int n_rows = in_sizes[1] / 4;   // 14400
    const int nt     = in_sizes[2];       // 800

    const int blocks = (n_rows + TILE_R - 1) / TILE_R;
    matcher_cost_kernel<<<blocks, THREADS>>>(logits, pboxes, labels, tboxes,
                                             out, n_rows, nt);
}

// round 9
// speedup vs baseline: 1.3135x; 1.3135x over previous
#include <cuda_runtime.h>
#include <cuda_bf16.h>

// HungarianMatcher cost tensor C[16,900,800], nc=256.
// R7 (resubmit after infra failure): 800 threads = 25 warps exactly.
// NT_PER=1 (zero lane waste, was 1.28x), TILE_R=25 (one softmax row per warp,
// 14400 = 576*25 exact), grid=576 -> ~1.9 waves at occ 2 (regs<=40 via
// launch_bounds). Attacks the ~19M warp-instr issue floor from the R5/R6
// wave refit.

constexpr int NC      = 256;
constexpr int TILE_R  = 25;    // query rows per block (one per warp)
constexpr int THREADS = 800;   // 25 warps

constexpr float EPS = 1e-7f;

__global__ __launch_bounds__(THREADS, 2)
void matcher_cost_kernel(const float* __restrict__ logits,   // [N, NC]
                         const float* __restrict__ pboxes,   // [N, 4]
                         const int*   __restrict__ labels,   // [nt]
                         const float* __restrict__ tboxes,   // [nt, 4]
                         float*       __restrict__ out,      // [N, nt]
                         int n_rows, int nt)
{
    __shared__ float  s_prob[TILE_R][NC];   // 25.6KB softmax probs
    __shared__ float4 s_pred[TILE_R][3];    // {cx,cy,w,h},{x0,y0,x1,y1},{area}

    const int tid  = threadIdx.x;
    const int lane = tid & 31;
    const int warp = tid >> 5;
    const int n0   = blockIdx.x * TILE_R;

    // --- Softmax: warp w owns row n0+w (256 classes, 8/lane via 2x float4) ---
    const int n = n0 + warp;
    if (n < n_rows) {
        const float4* lr4 = reinterpret_cast<const float4*>(logits + (size_t)n * NC);
        float4 a = lr4[lane];
        float4 b = lr4[lane + 32];
        float mx = fmaxf(fmaxf(fmaxf(a.x, a.y), fmaxf(a.z, a.w)),
                         fmaxf(fmaxf(b.x, b.y), fmaxf(b.z, b.w)));
        #pragma unroll
        for (int o = 16; o > 0; o >>= 1)
            mx = fmaxf(mx, __shfl_xor_sync(0xffffffffu, mx, o));
        a.x = __expf(a.x - mx); a.y = __expf(a.y - mx);
        a.z = __expf(a.z - mx); a.w = __expf(a.w - mx);
        b.x = __expf(b.x - mx); b.y = __expf(b.y - mx);
        b.z = __expf(b.z - mx); b.w = __expf(b.w - mx);
        float sum = (a.x + a.y) + (a.z + a.w) + (b.x + b.y) + (b.z + b.w);
        #pragma unroll
        for (int o = 16; o > 0; o >>= 1)
            sum += __shfl_xor_sync(0xffffffffu, sum, o);
        float inv = __fdividef(1.0f, sum);
        a.x *= inv; a.y *= inv; a.z *= inv; a.w *= inv;
        b.x *= inv; b.y *= inv; b.z *= inv; b.w *= inv;
        float4* pr = reinterpret_cast<float4*>(s_prob[warp]);
        pr[lane]      = a;
        pr[lane + 32] = b;

        if (lane == 0) {
            float4 pb = reinterpret_cast<const float4*>(pboxes)[n];
            float hw = 0.5f * pb.z, hh = 0.5f * pb.w;
            s_pred[warp][0] = pb;
            s_pred[warp][1] = make_float4(pb.x - hw, pb.y - hh, pb.x + hw, pb.y + hh);
            s_pred[warp][2] = make_float4(pb.z * pb.w, 0.f, 0.f, 0.f);
        }
    }
    __syncthreads();

    const int rmax = min(TILE_R, n_rows - n0);

    // --- Main loop: one target per thread, loop over the tile's rows ---
    // (outer m-loop runs once for nt=800; kept for generality)
    for (int m = tid; m < nt; m += THREADS) {
        // target -> 6 registers (half-width form; xyxy derived in-loop)
        float4 b = reinterpret_cast<const float4*>(tboxes)[m];
        const int   lob = labels[m] * 4;          // label byte offset
        const float tcx = b.x, tcy = b.y;
        const float thw = 0.5f * b.z, thh = 0.5f * b.w;
        const float ta  = b.z * b.w;

        const float tx0 = tcx - thw, tx1 = tcx + thw;
        const float ty0 = tcy - thh, ty1 = tcy + thh;
        const float tw2 = thw + thw, th2 = thh + thh;

        float* op = out + (size_t)n0 * nt + m;
        const char* prb = reinterpret_cast<const char*>(&s_prob[0][0]) + lob;

        #pragma unroll 5
        for (int r = 0; r < rmax; r++) {
            const float4 pc = s_pred[r][0];   // broadcast LDS.128
            const float4 px = s_pred[r][1];
            const float  pa = s_pred[r][2].x;
            float p = *reinterpret_cast<const float*>(prb);
            prb += NC * 4;

            float l1 = fabsf(pc.x - tcx) + fabsf(pc.y - tcy)
                     + fabsf(pc.z - tw2) + fabsf(pc.w - th2);

            float ix = fminf(px.z, tx1) - fmaxf(px.x, tx0);
            float iy = fminf(px.w, ty1) - fmaxf(px.y, ty0);
            float inter = fmaxf(ix, 0.f) * fmaxf(iy, 0.f);
            float uni   = pa + ta - inter;

            // enclosing box via min/max sum identity: cx = (pw + tw) - ix
            float cxv = (pc.z + tw2) - ix;
            float cyv = (pc.w + th2) - iy;
            float ca  = cxv * cyv;

            // giou = inter/u - (ca-uni)/c == (inter*c + (uni-ca)*u)/(u*c)
            float u = uni + EPS;
            float c = ca + EPS;
            float num = fmaf(uni - ca, u, inter * c);
            float giou = __fdividef(num, u * c);

            op[0] = fmaf(-2.f, giou, fmaf(5.f, l1, -p));
            op += nt;
        }
    }
}

extern "C" void kernel_launch(void* const* d_in, const int* in_sizes, int n_in,
                              void* d_out, int out_size)
{
    const float* logits = (const float*)d_in[0];
    const float* pboxes = (const float*)d_in[1];
    const int*   labels = (const int*)  d_in[2];
    const float* tboxes = (const float*)d_in[3];
    float*       out    = (float*)d_out;

    const int n_rows = in_sizes[1] / 4;   // 14400
    const int nt     = in_sizes[2];       // 800

    const int blocks = (n_rows + TILE_R - 1) / TILE_R;   // 576
    matcher_cost_kernel<<<blocks, THREADS>>>(logits, pboxes, labels, tboxes,
                                             out, n_rows, nt);
}

// round 12
// speedup vs baseline: 1.3253x; 1.0089x over previous
#include <cuda_runtime.h>
#include <cuda_bf16.h>

// HungarianMatcher cost tensor C[16,900,800], nc=256.
// R8: combine NT_PER=2 load amortization (R5) with near-zero lane waste (R7).
// 416 threads = 13 warps; main loop threads 0..399 own 2 targets each (3.8%
// waste vs R5's 28%); TILE_R=16 rows, softmax warps stride rows. grid=900 at
// occ 3 -> 1.97 waves. Per-output instr count ~36 vs R7's 42.

constexpr int NC      = 256;
constexpr int TILE_R  = 16;    // query rows per block
constexpr int THREADS = 416;   // 13 warps
constexpr int NWARPS  = THREADS / 32;
constexpr int NT_PER  = 2;     // targets per thread (800 = 400 * 2)

constexpr float EPS = 1e-7f;

__global__ __launch_bounds__(THREADS, 3)
void matcher_cost_kernel(const float* __restrict__ logits,   // [N, NC]
                         const float* __restrict__ pboxes,   // [N, 4]
                         const int*   __restrict__ labels,   // [nt]
                         const float* __restrict__ tboxes,   // [nt, 4]
                         float*       __restrict__ out,      // [N, nt]
                         int n_rows, int nt)
{
    __shared__ float  s_prob[TILE_R][NC];   // 16KB softmax probs
    __shared__ float4 s_pred[TILE_R][3];    // {cx,cy,w,h},{x0,y0,x1,y1},{area}

    const int tid  = threadIdx.x;
    const int lane = tid & 31;
    const int warp = tid >> 5;
    const int n0   = blockIdx.x * TILE_R;

    // --- Softmax: warps stride the tile's rows (16 rows over 13 warps) ---
    for (int rr = warp; rr < TILE_R; rr += NWARPS) {
        const int n = n0 + rr;
        if (n >= n_rows) break;
        const float4* lr4 = reinterpret_cast<const float4*>(logits + (size_t)n * NC);
        float4 a = lr4[lane];
        float4 b = lr4[lane + 32];
        float mx = fmaxf(fmaxf(fmaxf(a.x, a.y), fmaxf(a.z, a.w)),
                         fmaxf(fmaxf(b.x, b.y), fmaxf(b.z, b.w)));
        #pragma unroll
        for (int o = 16; o > 0; o >>= 1)
            mx = fmaxf(mx, __shfl_xor_sync(0xffffffffu, mx, o));
        a.x = __expf(a.x - mx); a.y = __expf(a.y - mx);
        a.z = __expf(a.z - mx); a.w = __expf(a.w - mx);
        b.x = __expf(b.x - mx); b.y = __expf(b.y - mx);
        b.z = __expf(b.z - mx); b.w = __expf(b.w - mx);
        float sum = (a.x + a.y) + (a.z + a.w) + (b.x + b.y) + (b.z + b.w);
        #pragma unroll
        for (int o = 16; o > 0; o >>= 1)
            sum += __shfl_xor_sync(0xffffffffu, sum, o);
        float inv = __fdividef(1.0f, sum);
        a.x *= inv; a.y *= inv; a.z *= inv; a.w *= inv;
        b.x *= inv; b.y *= inv; b.z *= inv; b.w *= inv;
        float4* pr = reinterpret_cast<float4*>(s_prob[rr]);
        pr[lane]      = a;
        pr[lane + 32] = b;

        if (lane == 0) {
            float4 pb = reinterpret_cast<const float4*>(pboxes)[n];
            float hw = 0.5f * pb.z, hh = 0.5f * pb.w;
            s_pred[rr][0] = pb;
            s_pred[rr][1] = make_float4(pb.x - hw, pb.y - hh, pb.x + hw, pb.y + hh);
            s_pred[rr][2] = make_float4(pb.z * pb.w, 0.f, 0.f, 0.f);
        }
    }
    __syncthreads();

    const int rmax = min(TILE_R, n_rows - n0);
    const int mbase = tid * NT_PER;

    if (mbase + NT_PER <= nt) {
        // --- Fast path: 2 targets in registers (full derived form) ---
        float tcx[NT_PER], tcy[NT_PER], tw2[NT_PER], th2[NT_PER];
        float tx0[NT_PER], ty0[NT_PER], tx1[NT_PER], ty1[NT_PER], ta[NT_PER];
        const float4* tb4 = reinterpret_cast<const float4*>(tboxes);
        int2 lb = reinterpret_cast<const int2*>(labels)[tid];
        #pragma unroll
        for (int j = 0; j < NT_PER; j++) {
            float4 b = tb4[mbase + j];
            tcx[j] = b.x; tcy[j] = b.y; tw2[j] = b.z; th2[j] = b.w;
            float hw = 0.5f * b.z, hh = 0.5f * b.w;
            tx0[j] = b.x - hw; ty0[j] = b.y - hh;
            tx1[j] = b.x + hw; ty1[j] = b.y + hh;
            ta[j]  = b.z * b.w;
        }
        const char* prb0 = reinterpret_cast<const char*>(&s_prob[0][0]) + lb.x * 4;
        const char* prb1 = reinterpret_cast<const char*>(&s_prob[0][0]) + lb.y * 4;
        float* op = out + (size_t)n0 * nt + mbase;

        #pragma unroll 4
        for (int r = 0; r < rmax; r++) {
            const float4 pc = s_pred[r][0];   // broadcast LDS.128
            const float4 px = s_pred[r][1];
            const float  pa = s_pred[r][2].x;
            float p0 = *reinterpret_cast<const float*>(prb0);
            float p1 = *reinterpret_cast<const float*>(prb1);
            prb0 += NC * 4; prb1 += NC * 4;
            float p[NT_PER] = {p0, p1};

            float res[NT_PER];
            #pragma unroll
            for (int j = 0; j < NT_PER; j++) {
                float l1 = fabsf(pc.x - tcx[j]) + fabsf(pc.y - tcy[j])
                         + fabsf(pc.z - tw2[j]) + fabsf(pc.w - th2[j]);

                float ix = fminf(px.z, tx1[j]) - fmaxf(px.x, tx0[j]);
                float iy = fminf(px.w, ty1[j]) - fmaxf(px.y, ty0[j]);
                float inter = fmaxf(ix, 0.f) * fmaxf(iy, 0.f);
                float uni   = pa + ta[j] - inter;

                // enclosing box via min/max sum identity: cx = (pw + tw) - ix
                float cxv = (pc.z + tw2[j]) - ix;
                float cyv = (pc.w + th2[j]) - iy;
                float ca  = cxv * cyv;

                // giou = inter/u - (ca-uni)/c == (inter*c + (uni-ca)*u)/(u*c)
                float u = uni + EPS;
                float c = ca + EPS;
                float num = fmaf(uni - ca, u, inter * c);
                float giou = __fdividef(num, u * c);

                res[j] = fmaf(-2.f, giou, fmaf(5.f, l1, -p[j]));
            }
            *reinterpret_cast<float2*>(op) = make_float2(res[0], res[1]);
            op += nt;
        }
    } else if (mbase < nt) {
        // generic tail (odd nt; unused for nt=800)
        for (int j = 0; j < NT_PER && mbase + j < nt; j++) {
            int m = mbase + j;
            float4 b = reinterpret_cast<const float4*>(tboxes)[m];
            int lbm = labels[m];
            float hw = 0.5f * b.z, hh = 0.5f * b.w;
            float bx0 = b.x - hw, by0 = b.y - hh, bx1 = b.x + hw, by1 = b.y + hh;
            float bar = b.z * b.w;
            for (int r = 0; r < rmax; r++) {
                float4 pc = s_pred[r][0];
                float4 px = s_pred[r][1];
                float  pa = s_pred[r][2].x;
                float pp = s_prob[r][lbm];
                float l1 = fabsf(pc.x - b.x) + fabsf(pc.y - b.y)
                         + fabsf(pc.z - b.z) + fabsf(pc.w - b.w);
                float ix = fminf(px.z, bx1) - fmaxf(px.x, bx0);
                float iy = fminf(px.w, by1) - fmaxf(px.y, by0);
                float inter = fmaxf(ix, 0.f) * fmaxf(iy, 0.f);
                float uni = pa + bar - inter;
                float iou = __fdividef(inter, uni + EPS);
                float cxv = fmaxf(px.z, bx1) - fminf(px.x, bx0);
                float cyv = fmaxf(px.w, by1) - fminf(px.y, by0);
                float ca = cxv * cyv;
                float giou = iou - __fdividef(ca - uni, ca + EPS);
                out[(size_t)(n0 + r) * nt + m] = 5.f * l1 - pp - 2.f * giou;
            }
        }
    }
}

extern "C" void kernel_launch(void* const* d_in, const int* in_sizes, int n_in,
                              void* d_out, int out_size)
{
    const float* logits = (const float*)d_in[0];
    const float* pboxes = (const float*)d_in[1];
    const int*   labels = (const int*)  d_in[2];
    const float* tboxes = (const float*)d_in[3];
    float*       out    = (float*)d_out;

    const int n_rows = in_sizes[1] / 4;   // 14400
    const int nt     = in_sizes[2];       // 800

    const int blocks = (n_rows + TILE_R - 1) / TILE_R;   // 900
    matcher_cost_kernel<<<blocks, THREADS>>>(logits, pboxes, labels, tboxes,
                                             out, n_rows, nt);
}

// round 13
// speedup vs baseline: 1.4451x; 1.0904x over previous
#include <cuda_runtime.h>
#include <cuda_bf16.h>

// HungarianMatcher cost tensor C[16,900,800], nc=256.
// R9: shape specialization. nt=800 baked as template constant + full unroll of
// the 16-row loop => all LDS/STG use immediate offsets, no pointer increments,
// no loop control. Kills the alu=25% address-math tax identified as the gap
// between measured 47 instrs/output and the ~33 static FP count. Also drops
// the s_pred area load (recompute pa = w*h, 1 FMUL).

constexpr int NC      = 256;
constexpr int TILE_R  = 16;    // query rows per block
constexpr int THREADS = 416;   // 13 warps
constexpr int NWARPS  = THREADS / 32;
constexpr int NT_PER  = 2;     // targets per thread (800 = 400 * 2)

constexpr float EPS = 1e-7f;

template<int NT>   // NT > 0: compile-time nt; NT == 0: dynamic fallback
__global__ __launch_bounds__(THREADS, 3)
void matcher_cost_kernel(const float* __restrict__ logits,   // [N, NC]
                         const float* __restrict__ pboxes,   // [N, 4]
                         const int*   __restrict__ labels,   // [nt]
                         const float* __restrict__ tboxes,   // [nt, 4]
                         float*       __restrict__ out,      // [N, nt]
                         int n_rows, int nt_dyn)
{
    const int nt = (NT > 0) ? NT : nt_dyn;

    __shared__ float  s_prob[TILE_R][NC];   // 16KB softmax probs
    __shared__ float4 s_pred[TILE_R][2];    // {cx,cy,w,h},{x0,y0,x1,y1}

    const int tid  = threadIdx.x;
    const int lane = tid & 31;
    const int warp = tid >> 5;
    const int n0   = blockIdx.x * TILE_R;

    // --- Softmax: warps stride the tile's rows (16 rows over 13 warps) ---
    for (int rr = warp; rr < TILE_R; rr += NWARPS) {
        const int n = n0 + rr;
        if (n >= n_rows) break;
        const float4* lr4 = reinterpret_cast<const float4*>(logits + (size_t)n * NC);
        float4 a = lr4[lane];
        float4 b = lr4[lane + 32];
        float mx = fmaxf(fmaxf(fmaxf(a.x, a.y), fmaxf(a.z, a.w)),
                         fmaxf(fmaxf(b.x, b.y), fmaxf(b.z, b.w)));
        #pragma unroll
        for (int o = 16; o > 0; o >>= 1)
            mx = fmaxf(mx, __shfl_xor_sync(0xffffffffu, mx, o));
        a.x = __expf(a.x - mx); a.y = __expf(a.y - mx);
        a.z = __expf(a.z - mx); a.w = __expf(a.w - mx);
        b.x = __expf(b.x - mx); b.y = __expf(b.y - mx);
        b.z = __expf(b.z - mx); b.w = __expf(b.w - mx);
        float sum = (a.x + a.y) + (a.z + a.w) + (b.x + b.y) + (b.z + b.w);
        #pragma unroll
        for (int o = 16; o > 0; o >>= 1)
            sum += __shfl_xor_sync(0xffffffffu, sum, o);
        float inv = __fdividef(1.0f, sum);
        a.x *= inv; a.y *= inv; a.z *= inv; a.w *= inv;
        b.x *= inv; b.y *= inv; b.z *= inv; b.w *= inv;
        float4* pr = reinterpret_cast<float4*>(s_prob[rr]);
        pr[lane]      = a;
        pr[lane + 32] = b;

        if (lane == 0) {
            float4 pb = reinterpret_cast<const float4*>(pboxes)[n];
            float hw = 0.5f * pb.z, hh = 0.5f * pb.w;
            s_pred[rr][0] = pb;
            s_pred[rr][1] = make_float4(pb.x - hw, pb.y - hh, pb.x + hw, pb.y + hh);
        }
    }
    __syncthreads();

    const int mbase = tid * NT_PER;
    const bool full_tile = (n0 + TILE_R) <= n_rows;   // always true: 14400 % 16 == 0

    if (mbase + NT_PER <= nt && full_tile) {
        // --- Fast path: 2 targets in registers, FULL unroll, immediate addrs ---
        float tcx[NT_PER], tcy[NT_PER], tw2[NT_PER], th2[NT_PER];
        float tx0[NT_PER], ty0[NT_PER], tx1[NT_PER], ty1[NT_PER], ta[NT_PER];
        const float4* tb4 = reinterpret_cast<const float4*>(tboxes);
        int2 lb = reinterpret_cast<const int2*>(labels)[tid];
        #pragma unroll
        for (int j = 0; j < NT_PER; j++) {
            float4 b = tb4[mbase + j];
            tcx[j] = b.x; tcy[j] = b.y; tw2[j] = b.z; th2[j] = b.w;
            float hw = 0.5f * b.z, hh = 0.5f * b.w;
            tx0[j] = b.x - hw; ty0[j] = b.y - hh;
            tx1[j] = b.x + hw; ty1[j] = b.y + hh;
            ta[j]  = b.z * b.w;
        }
        const float* pr0 = &s_prob[0][lb.x];   // row stride NC -> imm offsets
        const float* pr1 = &s_prob[0][lb.y];
        float* op = out + (size_t)n0 * nt + mbase;

        #pragma unroll
        for (int r = 0; r < TILE_R; r++) {
            const float4 pc = s_pred[r][0];    // LDS.128 [base + r*32]
            const float4 px = s_pred[r][1];
            const float  pa = pc.z * pc.w;
            const float p0 = pr0[r * NC];      // LDS.32 [base + r*1024]
            const float p1 = pr1[r * NC];

            float res0, res1;
            {
                float l1 = fabsf(pc.x - tcx[0]) + fabsf(pc.y - tcy[0])
                         + fabsf(pc.z - tw2[0]) + fabsf(pc.w - th2[0]);
                float ix = fminf(px.z, tx1[0]) - fmaxf(px.x, tx0[0]);
                float iy = fminf(px.w, ty1[0]) - fmaxf(px.y, ty0[0]);
                float inter = fmaxf(ix, 0.f) * fmaxf(iy, 0.f);
                float uni   = pa + ta[0] - inter;
                float cxv = (pc.z + tw2[0]) - ix;
                float cyv = (pc.w + th2[0]) - iy;
                float ca  = cxv * cyv;
                float u = uni + EPS, c = ca + EPS;
                float num = fmaf(uni - ca, u, inter * c);
                float giou = __fdividef(num, u * c);
                res0 = fmaf(-2.f, giou, fmaf(5.f, l1, -p0));
            }
            {
                float l1 = fabsf(pc.x - tcx[1]) + fabsf(pc.y - tcy[1])
                         + fabsf(pc.z - tw2[1]) + fabsf(pc.w - th2[1]);
                float ix = fminf(px.z, tx1[1]) - fmaxf(px.x, tx0[1]);
                float iy = fminf(px.w, ty1[1]) - fmaxf(px.y, ty0[1]);
                float inter = fmaxf(ix, 0.f) * fmaxf(iy, 0.f);
                float uni   = pa + ta[1] - inter;
                float cxv = (pc.z + tw2[1]) - ix;
                float cyv = (pc.w + th2[1]) - iy;
                float ca  = cxv * cyv;
                float u = uni + EPS, c = ca + EPS;
                float num = fmaf(uni - ca, u, inter * c);
                float giou = __fdividef(num, u * c);
                res1 = fmaf(-2.f, giou, fmaf(5.f, l1, -p1));
            }
            // STG.64 [base + r*nt*4] -- immediate when NT compile-time
            *reinterpret_cast<float2*>(op + (size_t)r * nt) = make_float2(res0, res1);
        }
    } else if (mbase < nt) {
        // generic path (partial tile or odd nt; unused for the bench shape)
        const int rmax = min(TILE_R, n_rows - n0);
        for (int j = 0; j < NT_PER && mbase + j < nt; j++) {
            int m = mbase + j;
            float4 b = reinterpret_cast<const float4*>(tboxes)[m];
            int lbm = labels[m];
            float hw = 0.5f * b.z, hh = 0.5f * b.w;
            float bx0 = b.x - hw, by0 = b.y - hh, bx1 = b.x + hw, by1 = b.y + hh;
            float bar = b.z * b.w;
            for (int r = 0; r < rmax; r++) {
                float4 pc = s_pred[r][0];
                float4 px = s_pred[r][1];
                float  pa = pc.z * pc.w;
                float pp = s_prob[r][lbm];
                float l1 = fabsf(pc.x - b.x) + fabsf(pc.y - b.y)
                         + fabsf(pc.z - b.z) + fabsf(pc.w - b.w);
                float ix = fminf(px.z, bx1) - fmaxf(px.x, bx0);
                float iy = fminf(px.w, by1) - fmaxf(px.y, by0);
                float inter = fmaxf(ix, 0.f) * fmaxf(iy, 0.f);
                float uni = pa + bar - inter;
                float iou = __fdividef(inter, uni + EPS);
                float cxv = fmaxf(px.z, bx1) - fminf(px.x, bx0);
                float cyv = fmaxf(px.w, by1) - fminf(px.y, by0);
                float ca = cxv * cyv;
                float giou = iou - __fdividef(ca - uni, ca + EPS);
                out[(size_t)(n0 + r) * nt + m] = 5.f * l1 - pp - 2.f * giou;
            }
        }
    }
}

extern "C" void kernel_launch(void* const* d_in, const int* in_sizes, int n_in,
                              void* d_out, int out_size)
{
    const float* logits = (const float*)d_in[0];
    const float* pboxes = (const float*)d_in[1];
    const int*   labels = (const int*)  d_in[2];
    const float* tboxes = (const float*)d_in[3];
    float*       out    = (float*)d_out;

    const int n_rows = in_sizes[1] / 4;   // 14400
    const int nt     = in_sizes[2];       // 800

    const int blocks = (n_rows + TILE_R - 1) / TILE_R;   // 900
    if (nt == 800) {
        matcher_cost_kernel<800><<<blocks, THREADS>>>(logits, pboxes, labels,
                                                      tboxes, out, n_rows, nt);
    } else {
        matcher_cost_kernel<0><<<blocks, THREADS>>>(logits, pboxes, labels,
                                                    tboxes, out, n_rows, nt);
    }
}